// round 13
// baseline (speedup 1.0000x reference)
#include <cuda_runtime.h>
#include <cuda_fp16.h>
#include <cstdint>

#define B_ 1024
#define N_ 128
#define H_ 128
#define D_ 8
#define NT 9   // 8 g col-tiles (128 cols) + 1 f tile

// Packed X operand (prep_x writes, main reads)
// g_xa: [mtile 4][chunk 8][m 256][k16] fp16 pairs (single-level X)
__device__ __align__(16) unsigned g_xa[4 * 8 * 256 * 8];           // 256KB

// ---------------- helpers ----------------
__device__ __forceinline__ uint32_t smem_u32(const void* p) {
    uint32_t a;
    asm("{ .reg .u64 t; cvta.to.shared.u64 t, %1; cvt.u32.u64 %0, t; }" : "=r"(a) : "l"(p));
    return a;
}
__device__ __forceinline__ unsigned pack_h2(__half a, __half b) {
    __half2 t = __halves2half2(a, b);
    return *reinterpret_cast<unsigned*>(&t);
}
__device__ __forceinline__ float elu1(float x) {
    return x > 0.0f ? x : (__expf(x) - 1.0f);
}

#define CP16(s, g) asm volatile("cp.async.cg.shared.global [%0], [%1], 16;" :: "r"(s), "l"(g))
#define CP_COMMIT() asm volatile("cp.async.commit_group;" ::: "memory")
#define CP_WAIT(n)  asm volatile("cp.async.wait_group %0;" :: "n"(n) : "memory")

#define LDM4(r0, r1, r2, r3, a) \
    asm volatile("ldmatrix.sync.aligned.m8n8.x4.shared.b16 {%0,%1,%2,%3}, [%4];" \
        : "=r"(r0), "=r"(r1), "=r"(r2), "=r"(r3) : "r"(a))

#define LDM4T(r0, r1, r2, r3, a) \
    asm volatile("ldmatrix.sync.aligned.m8n8.x4.trans.shared.b16 {%0,%1,%2,%3}, [%4];" \
        : "=r"(r0), "=r"(r1), "=r"(r2), "=r"(r3) : "r"(a))

#define MMA16816(c, a, b) \
    asm volatile("mma.sync.aligned.m16n8k16.row.col.f32.f16.f16.f32 " \
        "{%0,%1,%2,%3}, {%4,%5,%6,%7}, {%8,%9}, {%0,%1,%2,%3};" \
        : "+f"((c)[0]), "+f"((c)[1]), "+f"((c)[2]), "+f"((c)[3]) \
        : "r"((a)[0]), "r"((a)[1]), "r"((a)[2]), "r"((a)[3]), "r"((b)[0]), "r"((b)[1]))

// ---------------- prep: x -> g_xa (single-level fp16, BT=256 tiles) ----------
__global__ void prep_x(const float* __restrict__ x) {
    int idx = blockIdx.x * blockDim.x + threadIdx.x;       // one u32 each
    if (idx >= 65536) return;
    int mt = idx >> 14;             // 16384 u32 per m-tile
    int c  = (idx >> 11) & 7;       // chunk 0..7
    int m  = (idx >> 3) & 255;
    int p  = idx & 7;
    int row = mt * 256 + m;
    int kb = c * 16 + 2 * p;
    g_xa[idx] = pack_h2(__float2half_rn(x[row * 128 + kb]),
                        __float2half_rn(x[row * 128 + kb + 1]));
}

// ---------------- main fused kernel ----------------
// grid (4 m-tiles of 256 rows, 128 nodes), 512 threads = 16 warps (4/SMSP).
// Warp tile 32x64: warp_m = (wid&7)*32, warp_n = (wid>>3)*64.
// B staged in-kernel from fp32 weights: smem [k][n] fp16, 256B rows,
// XOR-16B swizzle keyed on (k mod 8); B fragments via ldmatrix.trans.
// smem: B0 32KB | B1 32KB | XA 64KB | Wg 512B | Wf 512B  (~129KB, 1 CTA/SM)
#define SM_B0 0
#define SM_B1 32768
#define SM_XA 65536
#define SM_WG 131072
#define SM_WF 131584
#define SM_TOT 132096

__global__ __launch_bounds__(512, 1)
void sde_main(const float* __restrict__ fw, const float* __restrict__ gw,
              const float* __restrict__ Wf, const float* __restrict__ bfv,
              const float* __restrict__ Wg, const float* __restrict__ bgv,
              float* __restrict__ fout, float* __restrict__ gout) {
    extern __shared__ char smem[];
    const uint32_t sb = smem_u32(smem);
    const int tid = threadIdx.x, l = tid & 31, wid = tid >> 5;
    const int i = blockIdx.y, b0 = blockIdx.x * 256;
    const int warp_m = (wid & 7) * 32;
    const int warp_n = (wid >> 3) * 64;
    float* Wg_s = (float*)(smem + SM_WG);
    float* Wf_s = (float*)(smem + SM_WF);

    // staging: pass p covers k-rows p*16 + wid (8 passes); lane covers 4 cols
    const int ncol = l * 4;                                      // fp32 col base
    const uint32_t swb = (uint32_t)((l * 8) ^ ((wid & 7) << 4)); // swizzled STS off

    // XA via cp.async (64KB)
    const char* asrc = (const char*)g_xa + (size_t)blockIdx.x * 65536;
#pragma unroll
    for (int j = 0; j < 8; ++j) {
        uint32_t off = (uint32_t)(j * 512 + tid) * 16;
        CP16(sb + SM_XA + off, asrc + off);
    }
    CP_COMMIT();

    // pre-stage B tile 0 (g tile 0: cols 0..127, row stride 1024)
    {
        const float* w0 = gw + (size_t)i * 131072;
#pragma unroll
        for (int p = 0; p < 8; ++p) {
            int k = p * 16 + wid;
            float4 v = *reinterpret_cast<const float4*>(w0 + (size_t)k * 1024 + ncol);
            uint2 h;
            h.x = pack_h2(__float2half_rn(v.x), __float2half_rn(v.y));
            h.y = pack_h2(__float2half_rn(v.z), __float2half_rn(v.w));
            *reinterpret_cast<uint2*>(smem + SM_B0 + k * 256 + swb) = h;
        }
    }
    if (tid < 128) { Wg_s[tid] = Wg[i * H_ + tid]; Wf_s[tid] = Wf[i * H_ + tid]; }
    CP_WAIT(0);
    __syncthreads();

    // fragment addressing constants
    const uint32_t aoff = (uint32_t)((warp_m + (l & 15)) * 32 + (l >> 4) * 16);
    const int kl   = (l & 7) + ((l >> 4) << 3);     // k-row within 16 for this lane
    const int jofs = (l >> 3) & 1;                  // n-block parity within LDM4T
    const int swl  = (l & 7) << 4;                  // swizzle term for LDM addresses

    float accg[4][2], accf[4];
#pragma unroll
    for (int r = 0; r < 4; ++r) { accg[r][0] = 0.f; accg[r][1] = 0.f; accf[r] = 0.f; }

    for (int t = 0; t < NT; ++t) {
        const uint32_t bbase = (uint32_t)((t & 1) ? SM_B1 : SM_B0);
        const uint32_t sbase = (uint32_t)((t & 1) ? SM_B0 : SM_B1);   // staging target (t+1)
        const bool stg = (t + 1 < NT);
        const float* wsrc = nullptr;
        int wstr = 0;
        if (stg) {
            if (t + 1 < 8) { wsrc = gw + (size_t)i * 131072 + (t + 1) * 128; wstr = 1024; }
            else           { wsrc = fw + (size_t)i * 16384;                  wstr = 128; }
        }

        float acc[8][2][4];
#pragma unroll
        for (int in = 0; in < 8; ++in)
#pragma unroll
            for (int im = 0; im < 2; ++im)
#pragma unroll
                for (int r = 0; r < 4; ++r) acc[in][im][r] = 0.f;

        float4 pa[2];

#pragma unroll
        for (int s = 0; s < 8; ++s) {
            // ---- staged W conversion for tile t+1 (lookahead 2 steps) ----
            if (stg) {
                if (s >= 2) {   // STS of pass s-2 (data in pa[(s-2)&1] == pa[s&1])
                    int k = (s - 2) * 16 + wid;
                    uint2 h;
                    h.x = pack_h2(__float2half_rn(pa[s & 1].x), __float2half_rn(pa[s & 1].y));
                    h.y = pack_h2(__float2half_rn(pa[s & 1].z), __float2half_rn(pa[s & 1].w));
                    *reinterpret_cast<uint2*>(smem + sbase + k * 256 + swb) = h;
                }
                {               // LDG pass s
                    int k = s * 16 + wid;
                    pa[s & 1] = *reinterpret_cast<const float4*>(wsrc + (size_t)k * wstr + ncol);
                }
            }

            // ---- MMA step ----
            const uint32_t ab = sb + SM_XA + (uint32_t)(s * 8192) + aoff;
            uint32_t af[2][4], bfr[8][2];
#pragma unroll
            for (int im = 0; im < 2; ++im)
                LDM4(af[im][0], af[im][1], af[im][2], af[im][3], ab + im * 512);
#pragma unroll
            for (int p = 0; p < 4; ++p) {
                uint32_t kk = (uint32_t)(s * 16 + kl);
                uint32_t roff = (uint32_t)(((warp_n + p * 16 + jofs * 8) * 2) ^ swl);
                LDM4T(bfr[2 * p][0], bfr[2 * p + 1][0],
                      bfr[2 * p][1], bfr[2 * p + 1][1],
                      sb + bbase + kk * 256 + roff);
            }
#pragma unroll
            for (int im = 0; im < 2; ++im)
#pragma unroll
                for (int in = 0; in < 8; ++in)
                    MMA16816(acc[in][im], af[im], bfr[in]);
        }

        // flush staged passes 6,7 (loaded at steps 6,7)
        if (stg) {
#pragma unroll
            for (int q = 0; q < 2; ++q) {
                int k = (6 + q) * 16 + wid;
                uint2 h;
                h.x = pack_h2(__float2half_rn(pa[q].x), __float2half_rn(pa[q].y));
                h.y = pack_h2(__float2half_rn(pa[q].z), __float2half_rn(pa[q].w));
                *reinterpret_cast<uint2*>(smem + sbase + k * 256 + swb) = h;
            }
        }

        // fused epilogue
        if (t < 8) {
            const int hb = t * 16 + (wid >> 3) * 8;
#pragma unroll
            for (int in = 0; in < 8; ++in) {
                const float w = Wg_s[hb + in];
#pragma unroll
                for (int im = 0; im < 2; ++im) {
                    accg[im * 2][0]     = fmaf(w, elu1(acc[in][im][0]), accg[im * 2][0]);
                    accg[im * 2][1]     = fmaf(w, elu1(acc[in][im][1]), accg[im * 2][1]);
                    accg[im * 2 + 1][0] = fmaf(w, elu1(acc[in][im][2]), accg[im * 2 + 1][0]);
                    accg[im * 2 + 1][1] = fmaf(w, elu1(acc[in][im][3]), accg[im * 2 + 1][1]);
                }
            }
        } else {
            const int cb = warp_n + 2 * (l & 3);
#pragma unroll
            for (int in = 0; in < 8; ++in) {
                const float w0 = Wf_s[cb + in * 8], w1 = Wf_s[cb + in * 8 + 1];
#pragma unroll
                for (int im = 0; im < 2; ++im) {
                    accf[im * 2]     += w0 * elu1(acc[in][im][0]) + w1 * elu1(acc[in][im][1]);
                    accf[im * 2 + 1] += w0 * elu1(acc[in][im][2]) + w1 * elu1(acc[in][im][3]);
                }
            }
        }
        __syncthreads();   // staged buffer complete + everyone done reading bbase
    }

    // cross-warp reduction: n-warps 8-15 hand partials to warps 0-7
    float* red = (float*)smem;                 // reuse B region
    const int base = ((wid & 7) * 32 + l) * 12;
    if (wid >= 8) {
#pragma unroll
        for (int r = 0; r < 4; ++r) {
            red[base + r * 2]     = accg[r][0];
            red[base + r * 2 + 1] = accg[r][1];
            red[base + 8 + r]     = accf[r];
        }
    }
    __syncthreads();
    if (wid < 8) {
        const float bgi = bgv[i], bfi = bfv[i];
#pragma unroll
        for (int r = 0; r < 4; ++r) {
            float g0 = accg[r][0] + red[base + r * 2];
            float g1 = accg[r][1] + red[base + r * 2 + 1];
            float vf = accf[r] + red[base + 8 + r];
            const int row = b0 + warp_m + (r >> 1) * 16 + (r & 1) * 8 + (l >> 2);
            *reinterpret_cast<float2*>(gout + ((size_t)row * 128 + i) * 8 + 2 * (l & 3)) =
                make_float2(g0 + bgi, g1 + bgi);
            vf += __shfl_xor_sync(0xffffffffu, vf, 1);
            vf += __shfl_xor_sync(0xffffffffu, vf, 2);
            if ((l & 3) == 0) fout[(size_t)row * 128 + i] = vf + bfi;
        }
    }
}

// ---------------- launch ----------------
extern "C" void kernel_launch(void* const* d_in, const int* in_sizes, int n_in,
                              void* d_out, int out_size) {
    (void)in_sizes; (void)n_in; (void)out_size;
    const float* x  = (const float*)d_in[0];
    const float* fw = (const float*)d_in[1];
    const float* gw = (const float*)d_in[2];
    const float* Wf = (const float*)d_in[3];
    const float* bf = (const float*)d_in[4];
    const float* Wg = (const float*)d_in[5];
    const float* bg = (const float*)d_in[6];
    float* out  = (float*)d_out;
    float* fout = out;                      // [B,N]
    float* gout = out + (size_t)B_ * N_;    // [B,N,D]

    static bool attr_set = false;
    if (!attr_set) {
        cudaFuncSetAttribute(sde_main, cudaFuncAttributeMaxDynamicSharedMemorySize, SM_TOT);
        attr_set = true;
    }

    prep_x<<<256, 256>>>(x);
    sde_main<<<dim3(4, N_), 512, SM_TOT>>>(fw, gw, Wf, bf, Wg, bg, fout, gout);
}